// round 1
// baseline (speedup 1.0000x reference)
#include <cuda_runtime.h>
#include <cstdint>

// Problem constants (shapes are fixed by the reference; nnz counts taken from in_sizes)
#define N_RES 8192
#define N_IN  256
#define BATCH 16

// Scratch (device globals — no allocation allowed in kernel_launch)
__device__ float g_ZT[N_RES * BATCH];   // accumulator, [row][b] layout, 64B per row
__device__ float g_ST[N_RES * BATCH];   // state transposed, [col][b]
__device__ float g_XT[N_IN * BATCH];    // x transposed, [col][b]

__device__ __forceinline__ void red_add_v4(float* addr, float a, float b, float c, float d) {
    asm volatile("red.global.add.v4.f32 [%0], {%1, %2, %3, %4};"
                 :: "l"(addr), "f"(a), "f"(b), "f"(c), "f"(d)
                 : "memory");
}

// Kernel A: transpose state -> ST, x -> XT, init ZT[r][b] = bias[r]
__global__ void prep_kernel(const float* __restrict__ state,
                            const float* __restrict__ x,
                            const float* __restrict__ bias) {
    int t = blockIdx.x * blockDim.x + threadIdx.x;
    if (t < N_RES * BATCH) {
        int b = t >> 13;          // t / 8192
        int r = t & (N_RES - 1);  // t % 8192
        float s = state[t];       // coalesced read of state[b][r]
        g_ST[r * BATCH + b] = s;
        g_ZT[r * BATCH + b] = bias[r];
    }
    if (t < N_IN * BATCH) {
        int b = t >> 8;           // t / 256
        int c = t & (N_IN - 1);   // t % 256
        g_XT[c * BATCH + b] = x[t];   // coalesced read of x[b][c]
    }
}

// Kernel B: one thread per nnz (reservoir nnz followed by input nnz).
// Gathers 16 batch values for this column, scales by val, vector-reduces
// into ZT[row][0..15] with 4x red.global.add.v4.f32.
__global__ void spmm_kernel(const float* __restrict__ res_vals,
                            const int*   __restrict__ res_rows,
                            const int*   __restrict__ res_cols,
                            const float* __restrict__ in_vals,
                            const int*   __restrict__ in_rows,
                            const int*   __restrict__ in_cols,
                            int nnz_res, int nnz_tot) {
    int i = blockIdx.x * blockDim.x + threadIdx.x;
    if (i >= nnz_tot) return;

    float val;
    int row;
    const float4* src;
    if (i < nnz_res) {
        val = res_vals[i];
        row = res_rows[i];
        int col = res_cols[i];
        src = reinterpret_cast<const float4*>(g_ST) + col * 4;
    } else {
        int j = i - nnz_res;
        val = in_vals[j];
        row = in_rows[j];
        int col = in_cols[j];
        src = reinterpret_cast<const float4*>(g_XT) + col * 4;
    }

    float4 s0 = src[0];
    float4 s1 = src[1];
    float4 s2 = src[2];
    float4 s3 = src[3];

    float* dst = g_ZT + row * BATCH;
    red_add_v4(dst +  0, val * s0.x, val * s0.y, val * s0.z, val * s0.w);
    red_add_v4(dst +  4, val * s1.x, val * s1.y, val * s1.z, val * s1.w);
    red_add_v4(dst +  8, val * s2.x, val * s2.y, val * s2.z, val * s2.w);
    red_add_v4(dst + 12, val * s3.x, val * s3.y, val * s3.z, val * s3.w);
}

// Kernel C: out[b][r] = erf(ZT[r][b])   (A_LEAK = 1 -> pure erf of z)
__global__ void finish_kernel(float* __restrict__ out) {
    int t = blockIdx.x * blockDim.x + threadIdx.x;
    if (t >= N_RES * BATCH) return;
    int b = t >> 13;
    int r = t & (N_RES - 1);
    out[t] = erff(g_ZT[r * BATCH + b]);  // coalesced write of out[b][r]
}

extern "C" void kernel_launch(void* const* d_in, const int* in_sizes, int n_in,
                              void* d_out, int out_size) {
    const float* state    = (const float*)d_in[0];
    const float* x        = (const float*)d_in[1];
    const float* res_vals = (const float*)d_in[2];
    const int*   res_rows = (const int*)  d_in[3];
    const int*   res_cols = (const int*)  d_in[4];
    const float* res_bias = (const float*)d_in[5];
    const float* in_vals  = (const float*)d_in[6];
    const int*   in_rows  = (const int*)  d_in[7];
    const int*   in_cols  = (const int*)  d_in[8];
    float* out = (float*)d_out;

    int nnz_res = in_sizes[2];
    int nnz_in  = in_sizes[6];
    int nnz_tot = nnz_res + nnz_in;

    const int TPB = 256;

    // A: prep (transpose + init accumulator with bias)
    prep_kernel<<<(N_RES * BATCH + TPB - 1) / TPB, TPB>>>(state, x, res_bias);

    // B: COO scatter-accumulate with vector global reductions
    spmm_kernel<<<(nnz_tot + TPB - 1) / TPB, TPB>>>(
        res_vals, res_rows, res_cols, in_vals, in_rows, in_cols,
        nnz_res, nnz_tot);

    // C: erf + transpose to output layout
    finish_kernel<<<(N_RES * BATCH + TPB - 1) / TPB, TPB>>>(out);
}